// round 5
// baseline (speedup 1.0000x reference)
#include <cuda_runtime.h>
#include <cstdint>

#define Nn 4096
#define WORDS 128          // 4096 bits / 32
#define TI 16              // i-rows per block (register blocking)
#define JSPLIT 4           // split j-range across blocks
#define PACK_BLOCKS 2048
#define ROWSUM_BLOCKS Nn
#define PREF_BLOCKS 256    // L2-prefetch blocks for W inside agg launch

// Scratch (device globals — no allocation allowed)
__device__ uint32_t g_bitsT[WORDS * Nn];   // plane-major: word w of row j at [w*Nn + j]
__device__ __align__(16) float g_e[Nn];    // row sums of edge_features
__device__ __align__(16) float g_agg[Nn];  // aggregated[i]
__device__ float g_sink[PREF_BLOCKS];      // prefetch sink (never read)

// ---------------------------------------------------------------------------
// K1 (fused): blocks [0, PACK_BLOCKS) bit-pack adjacency (diag bit cleared).
//   Software-pipelined: 4 LDG.128 issued back-to-back BEFORE any reduce_or
//   sync, guaranteeing MLP=4. Exact trip count (8 iters/warp), no bounds.
// blocks [PACK_BLOCKS, ...) row-sum E and zero g_agg.
// ---------------------------------------------------------------------------
__global__ void prep_kernel(const float* __restrict__ A,
                            const float* __restrict__ E) {
    if (blockIdx.x < PACK_BLOCKS) {
        int lane = threadIdx.x & 31;
        int warpid = blockIdx.x * 8 + (threadIdx.x >> 5);   // 0..16383
        const int NW = PACK_BLOCKS * 8;                     // 16384 warps
        unsigned q = lane >> 3;                             // word-in-group
        unsigned grpmask = 0xFFu << (q * 8);
        unsigned sh = (lane & 7) * 4;
        // NWG = Nn*32 = 131072 groups; exactly 8 per warp.
        for (int o = 0; o < 8; o += 4) {
            float4 v[4];
            int jj[4], wg[4], col[4];
            #pragma unroll
            for (int k = 0; k < 4; k++) {
                int gw = warpid + (o + k) * NW;
                jj[k]  = gw >> 5;
                wg[k]  = gw & 31;
                col[k] = (wg[k] << 7) + ((lane) << 2);
                v[k] = *(const float4*)(A + (size_t)jj[k] * Nn + col[k]);
            }
            #pragma unroll
            for (int k = 0; k < 4; k++) {
                unsigned nib = 0;
                if (v[k].x == 1.0f && col[k] + 0 != jj[k]) nib |= 1u;
                if (v[k].y == 1.0f && col[k] + 1 != jj[k]) nib |= 2u;
                if (v[k].z == 1.0f && col[k] + 2 != jj[k]) nib |= 4u;
                if (v[k].w == 1.0f && col[k] + 3 != jj[k]) nib |= 8u;
                unsigned word = __reduce_or_sync(grpmask, nib << sh);
                if ((lane & 7) == 0) {
                    int w = (wg[k] << 2) + (int)q;
                    g_bitsT[w * Nn + jj[k]] = word;
                }
            }
        }
    } else {
        int j = blockIdx.x - PACK_BLOCKS;
        const float4* row = (const float4*)(E + (size_t)j * Nn);
        int tid = threadIdx.x;
        float s = 0.f;
        #pragma unroll
        for (int k = 0; k < 4; k++) {
            float4 v = row[tid + 256 * k];
            s += (v.x + v.y) + (v.z + v.w);
        }
        s += __shfl_down_sync(0xffffffffu, s, 16);
        s += __shfl_down_sync(0xffffffffu, s, 8);
        s += __shfl_down_sync(0xffffffffu, s, 4);
        s += __shfl_down_sync(0xffffffffu, s, 2);
        s += __shfl_down_sync(0xffffffffu, s, 1);
        __shared__ float sp[8];
        int lane = tid & 31, wid = tid >> 5;
        if (lane == 0) sp[wid] = s;
        __syncthreads();
        if (tid == 0) {
            float t = 0.f;
            #pragma unroll
            for (int k = 0; k < 8; k++) t += sp[k];
            g_e[j] = t;
            g_agg[j] = 0.f;
        }
    }
}

// ---------------------------------------------------------------------------
// K2: agg[i] = sum_j [ (i!=j) && (B_i & B_j != empty) ] * e[j]
// Fast path: word0 AND != 0 (miss prob ~1e-4). Slow path: scan words 1..127.
// Diagonal handled ONCE post-loop (pair (i,i) contributes e[i] iff B_i != 0).
// blockIdx.y == 0: prefetch W into L2 (DRAM is otherwise idle here).
// ---------------------------------------------------------------------------
__global__ void agg_kernel(const float* __restrict__ Wm) {
    int tid = threadIdx.x;

    if (blockIdx.y == 0) {
        if (blockIdx.x >= PREF_BLOCKS) return;
        const float4* w4 = (const float4*)Wm;
        size_t base = (size_t)blockIdx.x * (Nn * Nn / 4 / PREF_BLOCKS) + tid;
        float s0 = 0.f, s1 = 0.f, s2 = 0.f, s3 = 0.f;
        #pragma unroll
        for (int k = 0; k < 64; k += 4) {
            float4 a = w4[base + (size_t)(k + 0) * 256];
            float4 b = w4[base + (size_t)(k + 1) * 256];
            float4 c = w4[base + (size_t)(k + 2) * 256];
            float4 d = w4[base + (size_t)(k + 3) * 256];
            s0 += a.x + a.y + a.z + a.w;
            s1 += b.x + b.y + b.z + b.w;
            s2 += c.x + c.y + c.z + c.w;
            s3 += d.x + d.y + d.z + d.w;
        }
        float s = (s0 + s1) + (s2 + s3);
        if (tid == 0) g_sink[blockIdx.x] = s;   // keep the loads live
        return;
    }

    __shared__ uint32_t sBi[TI * WORDS];
    __shared__ int sNe[TI];           // row-nonempty flag (for diag fix)
    __shared__ float sPart[8][TI];
    int i0 = blockIdx.x * TI;

    if (tid < TI) sNe[tid] = 0;
    __syncthreads();
    for (int idx = tid; idx < TI * WORDS; idx += blockDim.x) {
        int r = idx >> 7, w = idx & (WORDS - 1);
        uint32_t v = g_bitsT[w * Nn + i0 + r];
        sBi[idx] = v;
        if (v) sNe[r] = 1;            // benign same-value race
    }
    __syncthreads();

    uint32_t bi0[TI];
    float acc[TI];
    #pragma unroll
    for (int r = 0; r < TI; r++) { bi0[r] = sBi[r * WORDS]; acc[r] = 0.f; }

    int jBeg = (blockIdx.y - 1) * (Nn / JSPLIT);
    int jEnd = jBeg + (Nn / JSPLIT);
    for (int j = jBeg + tid; j < jEnd; j += blockDim.x) {
        uint32_t b0 = g_bitsT[j];     // word-0 plane: 16KB, cache-resident
        float e = g_e[j];
        unsigned zmask = 0;
        #pragma unroll
        for (int r = 0; r < TI; r++) {
            uint32_t t = bi0[r] & b0;
            if (t) acc[r] += e;
            else   zmask |= (1u << r);
        }
        if (zmask) {                  // rare (~1e-4 per pair)
            do {
                int r = __ffs(zmask) - 1;
                zmask &= zmask - 1;
                bool hit = false;
                for (int w = 1; w < WORDS; w++)
                    if (sBi[r * WORDS + w] & g_bitsT[w * Nn + j]) { hit = true; break; }
                if (hit) acc[r] += e;
            } while (zmask);
        }
    }

    int lane = tid & 31, wid = tid >> 5;
    #pragma unroll
    for (int r = 0; r < TI; r++) {
        float v = acc[r];
        v += __shfl_down_sync(0xffffffffu, v, 16);
        v += __shfl_down_sync(0xffffffffu, v, 8);
        v += __shfl_down_sync(0xffffffffu, v, 4);
        v += __shfl_down_sync(0xffffffffu, v, 2);
        v += __shfl_down_sync(0xffffffffu, v, 1);
        if (lane == 0) sPart[wid][r] = v;
    }
    __syncthreads();
    if (tid < TI) {
        float s = 0.f;
        #pragma unroll
        for (int w = 0; w < 8; w++) s += sPart[w][tid];
        // diagonal correction, applied exactly once (by the owning chunk)
        int i = i0 + tid;
        if (i >= jBeg && i < jEnd && sNe[tid]) s -= g_e[i];
        atomicAdd(&g_agg[i], s);
    }
}

// ---------------------------------------------------------------------------
// K3: out[o] = b[o] + dot(W[o,:], agg)   (one warp per row; W is L2-hot)
// ---------------------------------------------------------------------------
__global__ void gemv_kernel(const float* __restrict__ Wm,
                            const float* __restrict__ bias,
                            float* __restrict__ out) {
    int gw = (blockIdx.x * blockDim.x + threadIdx.x) >> 5;
    int lane = threadIdx.x & 31;
    if (gw >= Nn) return;
    const float4* wr = (const float4*)(Wm + (size_t)gw * Nn);
    const float4* ar = (const float4*)g_agg;
    float s0 = 0.f, s1 = 0.f, s2 = 0.f, s3 = 0.f;
    #pragma unroll
    for (int k = 0; k < 32; k += 4) {
        float4 w0 = wr[lane + 32 * (k + 0)];
        float4 w1 = wr[lane + 32 * (k + 1)];
        float4 w2 = wr[lane + 32 * (k + 2)];
        float4 w3 = wr[lane + 32 * (k + 3)];
        float4 a0 = ar[lane + 32 * (k + 0)];
        float4 a1 = ar[lane + 32 * (k + 1)];
        float4 a2 = ar[lane + 32 * (k + 2)];
        float4 a3 = ar[lane + 32 * (k + 3)];
        s0 += w0.x * a0.x + w0.y * a0.y + w0.z * a0.z + w0.w * a0.w;
        s1 += w1.x * a1.x + w1.y * a1.y + w1.z * a1.z + w1.w * a1.w;
        s2 += w2.x * a2.x + w2.y * a2.y + w2.z * a2.z + w2.w * a2.w;
        s3 += w3.x * a3.x + w3.y * a3.y + w3.z * a3.z + w3.w * a3.w;
    }
    float s = (s0 + s1) + (s2 + s3);
    s += __shfl_down_sync(0xffffffffu, s, 16);
    s += __shfl_down_sync(0xffffffffu, s, 8);
    s += __shfl_down_sync(0xffffffffu, s, 4);
    s += __shfl_down_sync(0xffffffffu, s, 2);
    s += __shfl_down_sync(0xffffffffu, s, 1);
    if (lane == 0) out[gw] = s + bias[gw];
}

extern "C" void kernel_launch(void* const* d_in, const int* in_sizes, int n_in,
                              void* d_out, int out_size) {
    const float* A  = (const float*)d_in[0];  // adjacency [N,N]
    const float* E  = (const float*)d_in[1];  // edge_features [N,F]
    const float* Wm = (const float*)d_in[2];  // W [OUT,N]
    const float* b  = (const float*)d_in[3];  // b [OUT]
    float* out = (float*)d_out;

    prep_kernel<<<PACK_BLOCKS + ROWSUM_BLOCKS, 256>>>(A, E);
    dim3 g2(Nn / TI, JSPLIT + 1);             // y==0: W prefetch; y>=1: compute
    agg_kernel<<<g2, 256>>>(Wm);
    gemv_kernel<<<(Nn * 32) / 256, 256>>>(Wm, b, out);
}

// round 6
// speedup vs baseline: 1.0667x; 1.0667x over previous
#include <cuda_runtime.h>
#include <cstdint>

#define Nn 4096
#define WORDS 128          // 4096 bits / 32
#define TI 16              // i-rows per block (register blocking)
#define JSPLIT 2           // split j-range across blocks
#define PACK_BLOCKS 2048
#define ROWSUM_BLOCKS Nn
#define PREF_BLOCKS 256    // L2-prefetch blocks for W inside agg launch

// Scratch (device globals — no allocation allowed)
__device__ uint32_t g_bitsT[WORDS * Nn];   // plane-major: word w of row j at [w*Nn + j]
__device__ __align__(16) float g_e[Nn];    // row sums of edge_features
__device__ __align__(16) float g_agg[Nn];  // aggregated[i]
__device__ float g_sink[PREF_BLOCKS];      // prefetch sink (never read)

// ---------------------------------------------------------------------------
// K1 (fused): blocks [0, PACK_BLOCKS) bit-pack adjacency (diag bit cleared).
//   Byte-per-thread: 2 independent LDG.128 per thread (8 cols -> 1 byte),
//   __reduce_or_sync over 4-lane groups assembles each 32-bit word.
//   Halves REDUX + STG count vs nibble version; MLP=2 without extra regs.
// blocks [PACK_BLOCKS, ...) row-sum E and zero g_agg.
// ---------------------------------------------------------------------------
__global__ void prep_kernel(const float* __restrict__ A,
                            const float* __restrict__ E) {
    if (blockIdx.x < PACK_BLOCKS) {
        int lane = threadIdx.x & 31;
        int warpid = blockIdx.x * 8 + (threadIdx.x >> 5);   // 0..16383
        const int NW = PACK_BLOCKS * 8;                     // 16384 warps
        unsigned q = lane >> 2;                             // word-in-group (0..7)
        unsigned grpmask = 0xFu << (q << 2);
        unsigned sh = (lane & 3) * 8;
        // groups of 256 cols: Nn*16 = 65536 total, exactly 4 per warp
        #pragma unroll
        for (int o = 0; o < 4; o++) {
            int gg  = warpid + o * NW;
            int j   = gg >> 4;
            int grp = gg & 15;
            int col = (grp << 8) + (lane << 3);
            const float4* p = (const float4*)(A + (size_t)j * Nn + col);
            float4 v0 = p[0];
            float4 v1 = p[1];
            unsigned byte = 0;
            if (v0.x == 1.0f && col + 0 != j) byte |= 1u;
            if (v0.y == 1.0f && col + 1 != j) byte |= 2u;
            if (v0.z == 1.0f && col + 2 != j) byte |= 4u;
            if (v0.w == 1.0f && col + 3 != j) byte |= 8u;
            if (v1.x == 1.0f && col + 4 != j) byte |= 16u;
            if (v1.y == 1.0f && col + 5 != j) byte |= 32u;
            if (v1.z == 1.0f && col + 6 != j) byte |= 64u;
            if (v1.w == 1.0f && col + 7 != j) byte |= 128u;
            unsigned word = __reduce_or_sync(grpmask, byte << sh);
            if ((lane & 3) == 0) {
                int w = (grp << 3) + (int)q;
                g_bitsT[w * Nn + j] = word;
            }
        }
    } else {
        int j = blockIdx.x - PACK_BLOCKS;
        const float4* row = (const float4*)(E + (size_t)j * Nn);
        int tid = threadIdx.x;
        float s = 0.f;
        #pragma unroll
        for (int k = 0; k < 4; k++) {
            float4 v = row[tid + 256 * k];
            s += (v.x + v.y) + (v.z + v.w);
        }
        s += __shfl_down_sync(0xffffffffu, s, 16);
        s += __shfl_down_sync(0xffffffffu, s, 8);
        s += __shfl_down_sync(0xffffffffu, s, 4);
        s += __shfl_down_sync(0xffffffffu, s, 2);
        s += __shfl_down_sync(0xffffffffu, s, 1);
        __shared__ float sp[8];
        int lane = tid & 31, wid = tid >> 5;
        if (lane == 0) sp[wid] = s;
        __syncthreads();
        if (tid == 0) {
            float t = 0.f;
            #pragma unroll
            for (int k = 0; k < 8; k++) t += sp[k];
            g_e[j] = t;
            g_agg[j] = 0.f;
        }
    }
}

// ---------------------------------------------------------------------------
// K2: agg[i] = sum_j [ (i!=j) && (B_i & B_j != empty) ] * e[j]
// Fast path: word0 AND != 0 (miss prob ~1e-4). Slow path: scan words 1..127.
// Diagonal handled ONCE post-loop (pair (i,i) contributes e[i] iff B_i != 0).
// blockIdx.y == 0: prefetch W into L2 (DRAM is otherwise idle here).
// ---------------------------------------------------------------------------
__global__ void agg_kernel(const float* __restrict__ Wm) {
    int tid = threadIdx.x;

    if (blockIdx.y == 0) {
        if (blockIdx.x >= PREF_BLOCKS) return;
        const float4* w4 = (const float4*)Wm;
        size_t base = (size_t)blockIdx.x * (Nn * Nn / 4 / PREF_BLOCKS) + tid;
        float s0 = 0.f, s1 = 0.f, s2 = 0.f, s3 = 0.f;
        #pragma unroll
        for (int k = 0; k < 64; k += 4) {
            float4 a = w4[base + (size_t)(k + 0) * 256];
            float4 b = w4[base + (size_t)(k + 1) * 256];
            float4 c = w4[base + (size_t)(k + 2) * 256];
            float4 d = w4[base + (size_t)(k + 3) * 256];
            s0 += a.x + a.y + a.z + a.w;
            s1 += b.x + b.y + b.z + b.w;
            s2 += c.x + c.y + c.z + c.w;
            s3 += d.x + d.y + d.z + d.w;
        }
        float s = (s0 + s1) + (s2 + s3);
        if (tid == 0) g_sink[blockIdx.x] = s;   // keep the loads live
        return;
    }

    __shared__ uint32_t sBi[TI * WORDS];
    __shared__ int sNe[TI];           // row-nonempty flag (for diag fix)
    __shared__ float sPart[8][TI];
    int i0 = blockIdx.x * TI;

    if (tid < TI) sNe[tid] = 0;
    __syncthreads();
    for (int idx = tid; idx < TI * WORDS; idx += blockDim.x) {
        int r = idx >> 7, w = idx & (WORDS - 1);
        uint32_t v = g_bitsT[w * Nn + i0 + r];
        sBi[idx] = v;
        if (v) sNe[r] = 1;            // benign same-value race
    }
    __syncthreads();

    uint32_t bi0[TI];
    float acc[TI];
    #pragma unroll
    for (int r = 0; r < TI; r++) { bi0[r] = sBi[r * WORDS]; acc[r] = 0.f; }

    int jBeg = (blockIdx.y - 1) * (Nn / JSPLIT);
    int jEnd = jBeg + (Nn / JSPLIT);
    for (int j = jBeg + tid; j < jEnd; j += blockDim.x) {
        uint32_t b0 = g_bitsT[j];     // word-0 plane: 16KB, cache-resident
        float e = g_e[j];
        unsigned zmask = 0;
        #pragma unroll
        for (int r = 0; r < TI; r++) {
            uint32_t t = bi0[r] & b0;
            if (t) acc[r] += e;
            else   zmask |= (1u << r);
        }
        if (zmask) {                  // rare (~1e-4 per pair)
            do {
                int r = __ffs(zmask) - 1;
                zmask &= zmask - 1;
                bool hit = false;
                for (int w = 1; w < WORDS; w++)
                    if (sBi[r * WORDS + w] & g_bitsT[w * Nn + j]) { hit = true; break; }
                if (hit) acc[r] += e;
            } while (zmask);
        }
    }

    int lane = tid & 31, wid = tid >> 5;
    #pragma unroll
    for (int r = 0; r < TI; r++) {
        float v = acc[r];
        v += __shfl_down_sync(0xffffffffu, v, 16);
        v += __shfl_down_sync(0xffffffffu, v, 8);
        v += __shfl_down_sync(0xffffffffu, v, 4);
        v += __shfl_down_sync(0xffffffffu, v, 2);
        v += __shfl_down_sync(0xffffffffu, v, 1);
        if (lane == 0) sPart[wid][r] = v;
    }
    __syncthreads();
    if (tid < TI) {
        float s = 0.f;
        #pragma unroll
        for (int w = 0; w < 8; w++) s += sPart[w][tid];
        // diagonal correction, applied exactly once (by the owning chunk)
        int i = i0 + tid;
        if (i >= jBeg && i < jEnd && sNe[tid]) s -= g_e[i];
        atomicAdd(&g_agg[i], s);
    }
}

// ---------------------------------------------------------------------------
// K3: out[o] = b[o] + dot(W[o,:], agg)   (one warp per row; W is L2-hot)
// ---------------------------------------------------------------------------
__global__ void gemv_kernel(const float* __restrict__ Wm,
                            const float* __restrict__ bias,
                            float* __restrict__ out) {
    int gw = (blockIdx.x * blockDim.x + threadIdx.x) >> 5;
    int lane = threadIdx.x & 31;
    if (gw >= Nn) return;
    const float4* wr = (const float4*)(Wm + (size_t)gw * Nn);
    const float4* ar = (const float4*)g_agg;
    float s0 = 0.f, s1 = 0.f, s2 = 0.f, s3 = 0.f;
    #pragma unroll
    for (int k = 0; k < 32; k += 4) {
        float4 w0 = wr[lane + 32 * (k + 0)];
        float4 w1 = wr[lane + 32 * (k + 1)];
        float4 w2 = wr[lane + 32 * (k + 2)];
        float4 w3 = wr[lane + 32 * (k + 3)];
        float4 a0 = ar[lane + 32 * (k + 0)];
        float4 a1 = ar[lane + 32 * (k + 1)];
        float4 a2 = ar[lane + 32 * (k + 2)];
        float4 a3 = ar[lane + 32 * (k + 3)];
        s0 += w0.x * a0.x + w0.y * a0.y + w0.z * a0.z + w0.w * a0.w;
        s1 += w1.x * a1.x + w1.y * a1.y + w1.z * a1.z + w1.w * a1.w;
        s2 += w2.x * a2.x + w2.y * a2.y + w2.z * a2.z + w2.w * a2.w;
        s3 += w3.x * a3.x + w3.y * a3.y + w3.z * a3.z + w3.w * a3.w;
    }
    float s = (s0 + s1) + (s2 + s3);
    s += __shfl_down_sync(0xffffffffu, s, 16);
    s += __shfl_down_sync(0xffffffffu, s, 8);
    s += __shfl_down_sync(0xffffffffu, s, 4);
    s += __shfl_down_sync(0xffffffffu, s, 2);
    s += __shfl_down_sync(0xffffffffu, s, 1);
    if (lane == 0) out[gw] = s + bias[gw];
}

extern "C" void kernel_launch(void* const* d_in, const int* in_sizes, int n_in,
                              void* d_out, int out_size) {
    const float* A  = (const float*)d_in[0];  // adjacency [N,N]
    const float* E  = (const float*)d_in[1];  // edge_features [N,F]
    const float* Wm = (const float*)d_in[2];  // W [OUT,N]
    const float* b  = (const float*)d_in[3];  // b [OUT]
    float* out = (float*)d_out;

    prep_kernel<<<PACK_BLOCKS + ROWSUM_BLOCKS, 256>>>(A, E);
    dim3 g2(Nn / TI, JSPLIT + 1);             // y==0: W prefetch; y>=1: compute
    agg_kernel<<<g2, 256>>>(Wm);
    gemv_kernel<<<(Nn * 32) / 256, 256>>>(Wm, b, out);
}

// round 7
// speedup vs baseline: 1.1026x; 1.0337x over previous
#include <cuda_runtime.h>
#include <cstdint>

#define Nn 4096
#define WORDS 128          // 4096 bits / 32
#define TI 16              // i-rows per block (register blocking)
#define JSPLIT 2           // split j-range across blocks
#define PACK_BLOCKS 2048
#define ROWSUM_BLOCKS Nn
#define PREF_BLOCKS 256    // L2-prefetch blocks for W inside agg launch

// Scratch (device globals — no allocation allowed)
__device__ uint32_t g_bitsT[WORDS * Nn];   // plane-major: word w of row j at [w*Nn + j]
__device__ __align__(16) float g_e[Nn];    // row sums of edge_features
__device__ __align__(16) float g_agg[Nn];  // aggregated[i]
__device__ float g_sink[PREF_BLOCKS];      // prefetch sink (never read)

// ---------------------------------------------------------------------------
// K1 (fused): blocks [0, PACK_BLOCKS) bit-pack adjacency (diag bit cleared).
//   Byte-per-thread: 2 independent LDG.128 per thread (8 cols -> 1 byte),
//   __reduce_or_sync over 4-lane groups assembles each 32-bit word.
//   Halves REDUX + STG count vs nibble version; MLP=2 without extra regs.
// blocks [PACK_BLOCKS, ...) row-sum E and zero g_agg.
// ---------------------------------------------------------------------------
__global__ void prep_kernel(const float* __restrict__ A,
                            const float* __restrict__ E) {
    if (blockIdx.x < PACK_BLOCKS) {
        int lane = threadIdx.x & 31;
        int warpid = blockIdx.x * 8 + (threadIdx.x >> 5);   // 0..16383
        const int NW = PACK_BLOCKS * 8;                     // 16384 warps
        unsigned q = lane >> 2;                             // word-in-group (0..7)
        unsigned grpmask = 0xFu << (q << 2);
        unsigned sh = (lane & 3) * 8;
        // groups of 256 cols: Nn*16 = 65536 total, exactly 4 per warp
        #pragma unroll
        for (int o = 0; o < 4; o++) {
            int gg  = warpid + o * NW;
            int j   = gg >> 4;
            int grp = gg & 15;
            int col = (grp << 8) + (lane << 3);
            const float4* p = (const float4*)(A + (size_t)j * Nn + col);
            float4 v0 = p[0];
            float4 v1 = p[1];
            unsigned byte = 0;
            if (v0.x == 1.0f && col + 0 != j) byte |= 1u;
            if (v0.y == 1.0f && col + 1 != j) byte |= 2u;
            if (v0.z == 1.0f && col + 2 != j) byte |= 4u;
            if (v0.w == 1.0f && col + 3 != j) byte |= 8u;
            if (v1.x == 1.0f && col + 4 != j) byte |= 16u;
            if (v1.y == 1.0f && col + 5 != j) byte |= 32u;
            if (v1.z == 1.0f && col + 6 != j) byte |= 64u;
            if (v1.w == 1.0f && col + 7 != j) byte |= 128u;
            unsigned word = __reduce_or_sync(grpmask, byte << sh);
            if ((lane & 3) == 0) {
                int w = (grp << 3) + (int)q;
                g_bitsT[w * Nn + j] = word;
            }
        }
    } else {
        int j = blockIdx.x - PACK_BLOCKS;
        const float4* row = (const float4*)(E + (size_t)j * Nn);
        int tid = threadIdx.x;
        float s = 0.f;
        #pragma unroll
        for (int k = 0; k < 4; k++) {
            float4 v = row[tid + 256 * k];
            s += (v.x + v.y) + (v.z + v.w);
        }
        s += __shfl_down_sync(0xffffffffu, s, 16);
        s += __shfl_down_sync(0xffffffffu, s, 8);
        s += __shfl_down_sync(0xffffffffu, s, 4);
        s += __shfl_down_sync(0xffffffffu, s, 2);
        s += __shfl_down_sync(0xffffffffu, s, 1);
        __shared__ float sp[8];
        int lane = tid & 31, wid = tid >> 5;
        if (lane == 0) sp[wid] = s;
        __syncthreads();
        if (tid == 0) {
            float t = 0.f;
            #pragma unroll
            for (int k = 0; k < 8; k++) t += sp[k];
            g_e[j] = t;
            g_agg[j] = 0.f;
        }
    }
}

// ---------------------------------------------------------------------------
// K2: agg[i] = sum_j [ (i!=j) && (B_i & B_j != empty) ] * e[j]
// Fast path: word0 AND != 0 (miss prob ~1e-4). Slow path: scan words 1..127.
// Diagonal handled ONCE post-loop (pair (i,i) contributes e[i] iff B_i != 0).
// blockIdx.y == 0: prefetch W into L2 (DRAM is otherwise idle here).
// ---------------------------------------------------------------------------
__global__ void agg_kernel(const float* __restrict__ Wm) {
    int tid = threadIdx.x;

    if (blockIdx.y == 0) {
        if (blockIdx.x >= PREF_BLOCKS) return;
        const float4* w4 = (const float4*)Wm;
        size_t base = (size_t)blockIdx.x * (Nn * Nn / 4 / PREF_BLOCKS) + tid;
        float s0 = 0.f, s1 = 0.f, s2 = 0.f, s3 = 0.f;
        #pragma unroll
        for (int k = 0; k < 64; k += 4) {
            float4 a = w4[base + (size_t)(k + 0) * 256];
            float4 b = w4[base + (size_t)(k + 1) * 256];
            float4 c = w4[base + (size_t)(k + 2) * 256];
            float4 d = w4[base + (size_t)(k + 3) * 256];
            s0 += a.x + a.y + a.z + a.w;
            s1 += b.x + b.y + b.z + b.w;
            s2 += c.x + c.y + c.z + c.w;
            s3 += d.x + d.y + d.z + d.w;
        }
        float s = (s0 + s1) + (s2 + s3);
        if (tid == 0) g_sink[blockIdx.x] = s;   // keep the loads live
        return;
    }

    __shared__ uint32_t sBi[TI * WORDS];
    __shared__ int sNe[TI];           // row-nonempty flag (for diag fix)
    __shared__ float sPart[8][TI];
    int i0 = blockIdx.x * TI;

    if (tid < TI) sNe[tid] = 0;
    __syncthreads();
    for (int idx = tid; idx < TI * WORDS; idx += blockDim.x) {
        int r = idx >> 7, w = idx & (WORDS - 1);
        uint32_t v = g_bitsT[w * Nn + i0 + r];
        sBi[idx] = v;
        if (v) sNe[r] = 1;            // benign same-value race
    }
    __syncthreads();

    uint32_t bi0[TI];
    float acc[TI];
    #pragma unroll
    for (int r = 0; r < TI; r++) { bi0[r] = sBi[r * WORDS]; acc[r] = 0.f; }

    int jBeg = (blockIdx.y - 1) * (Nn / JSPLIT);
    int jEnd = jBeg + (Nn / JSPLIT);
    for (int j = jBeg + tid; j < jEnd; j += blockDim.x) {
        uint32_t b0 = g_bitsT[j];     // word-0 plane: 16KB, cache-resident
        float e = g_e[j];
        unsigned zmask = 0;
        #pragma unroll
        for (int r = 0; r < TI; r++) {
            uint32_t t = bi0[r] & b0;
            if (t) acc[r] += e;
            else   zmask |= (1u << r);
        }
        if (zmask) {                  // rare (~1e-4 per pair)
            do {
                int r = __ffs(zmask) - 1;
                zmask &= zmask - 1;
                bool hit = false;
                for (int w = 1; w < WORDS; w++)
                    if (sBi[r * WORDS + w] & g_bitsT[w * Nn + j]) { hit = true; break; }
                if (hit) acc[r] += e;
            } while (zmask);
        }
    }

    int lane = tid & 31, wid = tid >> 5;
    #pragma unroll
    for (int r = 0; r < TI; r++) {
        float v = acc[r];
        v += __shfl_down_sync(0xffffffffu, v, 16);
        v += __shfl_down_sync(0xffffffffu, v, 8);
        v += __shfl_down_sync(0xffffffffu, v, 4);
        v += __shfl_down_sync(0xffffffffu, v, 2);
        v += __shfl_down_sync(0xffffffffu, v, 1);
        if (lane == 0) sPart[wid][r] = v;
    }
    __syncthreads();
    if (tid < TI) {
        float s = 0.f;
        #pragma unroll
        for (int w = 0; w < 8; w++) s += sPart[w][tid];
        // diagonal correction, applied exactly once (by the owning chunk)
        int i = i0 + tid;
        if (i >= jBeg && i < jEnd && sNe[tid]) s -= g_e[i];
        atomicAdd(&g_agg[i], s);
    }
}

// ---------------------------------------------------------------------------
// K3: out[o] = b[o] + dot(W[o,:], agg)   (one warp per row; W is L2-hot)
// ---------------------------------------------------------------------------
__global__ void gemv_kernel(const float* __restrict__ Wm,
                            const float* __restrict__ bias,
                            float* __restrict__ out) {
    int gw = (blockIdx.x * blockDim.x + threadIdx.x) >> 5;
    int lane = threadIdx.x & 31;
    if (gw >= Nn) return;
    const float4* wr = (const float4*)(Wm + (size_t)gw * Nn);
    const float4* ar = (const float4*)g_agg;
    float s0 = 0.f, s1 = 0.f, s2 = 0.f, s3 = 0.f;
    #pragma unroll
    for (int k = 0; k < 32; k += 4) {
        float4 w0 = wr[lane + 32 * (k + 0)];
        float4 w1 = wr[lane + 32 * (k + 1)];
        float4 w2 = wr[lane + 32 * (k + 2)];
        float4 w3 = wr[lane + 32 * (k + 3)];
        float4 a0 = ar[lane + 32 * (k + 0)];
        float4 a1 = ar[lane + 32 * (k + 1)];
        float4 a2 = ar[lane + 32 * (k + 2)];
        float4 a3 = ar[lane + 32 * (k + 3)];
        s0 += w0.x * a0.x + w0.y * a0.y + w0.z * a0.z + w0.w * a0.w;
        s1 += w1.x * a1.x + w1.y * a1.y + w1.z * a1.z + w1.w * a1.w;
        s2 += w2.x * a2.x + w2.y * a2.y + w2.z * a2.z + w2.w * a2.w;
        s3 += w3.x * a3.x + w3.y * a3.y + w3.z * a3.z + w3.w * a3.w;
    }
    float s = (s0 + s1) + (s2 + s3);
    s += __shfl_down_sync(0xffffffffu, s, 16);
    s += __shfl_down_sync(0xffffffffu, s, 8);
    s += __shfl_down_sync(0xffffffffu, s, 4);
    s += __shfl_down_sync(0xffffffffu, s, 2);
    s += __shfl_down_sync(0xffffffffu, s, 1);
    if (lane == 0) out[gw] = s + bias[gw];
}

extern "C" void kernel_launch(void* const* d_in, const int* in_sizes, int n_in,
                              void* d_out, int out_size) {
    const float* A  = (const float*)d_in[0];  // adjacency [N,N]
    const float* E  = (const float*)d_in[1];  // edge_features [N,F]
    const float* Wm = (const float*)d_in[2];  // W [OUT,N]
    const float* b  = (const float*)d_in[3];  // b [OUT]
    float* out = (float*)d_out;

    prep_kernel<<<PACK_BLOCKS + ROWSUM_BLOCKS, 256>>>(A, E);
    dim3 g2(Nn / TI, JSPLIT + 1);             // y==0: W prefetch; y>=1: compute
    agg_kernel<<<g2, 256>>>(Wm);
    gemv_kernel<<<(Nn * 32) / 256, 256>>>(Wm, b, out);
}

// round 8
// speedup vs baseline: 1.1366x; 1.0309x over previous
#include <cuda_runtime.h>
#include <cstdint>

#define Nn 4096
#define WORDS 128          // 4096 bits / 32
#define TI 16              // i-rows per block (register blocking)
#define JSPLIT 2           // split j-range across blocks
#define PACK_BLOCKS 4096   // 16KB of A per block — balanced vs rowsum blocks
#define ROWSUM_BLOCKS Nn
#define PREF_BLOCKS 256    // L2-prefetch blocks for W inside agg launch

// Scratch (device globals — no allocation allowed)
__device__ uint32_t g_bitsT[WORDS * Nn];   // plane-major: word w of row j at [w*Nn + j]
__device__ __align__(16) float g_e[Nn];    // row sums of edge_features
__device__ __align__(16) float g_agg[Nn];  // aggregated[i]
__device__ float g_sink[PREF_BLOCKS];      // prefetch sink (never read)

// ---------------------------------------------------------------------------
// K1 (fused): blocks [0, PACK_BLOCKS) bit-pack adjacency (diag bit cleared).
//   Byte-per-thread: 2 LDG.128 per thread (8 cols -> 1 byte), reduce_or over
//   4-lane groups assembles each 32-bit word. 2 groups per warp.
// blocks [PACK_BLOCKS, ...) row-sum E and zero g_agg. Halves now balanced.
// ---------------------------------------------------------------------------
__global__ void prep_kernel(const float* __restrict__ A,
                            const float* __restrict__ E) {
    if (blockIdx.x < PACK_BLOCKS) {
        int lane = threadIdx.x & 31;
        int warpid = blockIdx.x * 8 + (threadIdx.x >> 5);   // 0..32767
        const int NW = PACK_BLOCKS * 8;                     // 32768 warps
        unsigned q = lane >> 2;                             // word-in-group (0..7)
        unsigned grpmask = 0xFu << (q << 2);
        unsigned sh = (lane & 3) * 8;
        // groups of 256 cols: Nn*16 = 65536 total, exactly 2 per warp
        #pragma unroll
        for (int o = 0; o < 2; o++) {
            int gg  = warpid + o * NW;
            int j   = gg >> 4;
            int grp = gg & 15;
            int col = (grp << 8) + (lane << 3);
            const float4* p = (const float4*)(A + (size_t)j * Nn + col);
            float4 v0 = p[0];
            float4 v1 = p[1];
            unsigned byte = 0;
            if (v0.x == 1.0f && col + 0 != j) byte |= 1u;
            if (v0.y == 1.0f && col + 1 != j) byte |= 2u;
            if (v0.z == 1.0f && col + 2 != j) byte |= 4u;
            if (v0.w == 1.0f && col + 3 != j) byte |= 8u;
            if (v1.x == 1.0f && col + 4 != j) byte |= 16u;
            if (v1.y == 1.0f && col + 5 != j) byte |= 32u;
            if (v1.z == 1.0f && col + 6 != j) byte |= 64u;
            if (v1.w == 1.0f && col + 7 != j) byte |= 128u;
            unsigned word = __reduce_or_sync(grpmask, byte << sh);
            if ((lane & 3) == 0) {
                int w = (grp << 3) + (int)q;
                g_bitsT[w * Nn + j] = word;
            }
        }
    } else {
        int j = blockIdx.x - PACK_BLOCKS;
        const float4* row = (const float4*)(E + (size_t)j * Nn);
        int tid = threadIdx.x;
        float s = 0.f;
        #pragma unroll
        for (int k = 0; k < 4; k++) {
            float4 v = row[tid + 256 * k];
            s += (v.x + v.y) + (v.z + v.w);
        }
        s += __shfl_down_sync(0xffffffffu, s, 16);
        s += __shfl_down_sync(0xffffffffu, s, 8);
        s += __shfl_down_sync(0xffffffffu, s, 4);
        s += __shfl_down_sync(0xffffffffu, s, 2);
        s += __shfl_down_sync(0xffffffffu, s, 1);
        __shared__ float sp[8];
        int lane = tid & 31, wid = tid >> 5;
        if (lane == 0) sp[wid] = s;
        __syncthreads();
        if (tid == 0) {
            float t = 0.f;
            #pragma unroll
            for (int k = 0; k < 8; k++) t += sp[k];
            g_e[j] = t;
            g_agg[j] = 0.f;
        }
    }
}

// ---------------------------------------------------------------------------
// K2: agg[i] = sum_j [ (i!=j) && (B_i & B_j != empty) ] * e[j]
// SUBTRACT-ON-MISS: acc[r] starts at this thread's sumE; the common path is
// just the word0 AND test (miss prob ~1e-4). On miss, scan words 1..127 and
// subtract e[j] only for true non-neighbors. No FADD / e-load on fast path.
// Diagonal handled once post-loop (pair (i,i) counts e[i] iff B_i != 0).
// blockIdx.y == 0: prefetch W into L2 (DRAM is otherwise idle here).
// ---------------------------------------------------------------------------
__global__ void agg_kernel(const float* __restrict__ Wm) {
    int tid = threadIdx.x;

    if (blockIdx.y == 0) {
        if (blockIdx.x >= PREF_BLOCKS) return;
        const float4* w4 = (const float4*)Wm;
        size_t base = (size_t)blockIdx.x * (Nn * Nn / 4 / PREF_BLOCKS) + tid;
        float s0 = 0.f, s1 = 0.f, s2 = 0.f, s3 = 0.f;
        #pragma unroll
        for (int k = 0; k < 64; k += 4) {
            float4 a = w4[base + (size_t)(k + 0) * 256];
            float4 b = w4[base + (size_t)(k + 1) * 256];
            float4 c = w4[base + (size_t)(k + 2) * 256];
            float4 d = w4[base + (size_t)(k + 3) * 256];
            s0 += a.x + a.y + a.z + a.w;
            s1 += b.x + b.y + b.z + b.w;
            s2 += c.x + c.y + c.z + c.w;
            s3 += d.x + d.y + d.z + d.w;
        }
        float s = (s0 + s1) + (s2 + s3);
        if (tid == 0) g_sink[blockIdx.x] = s;   // keep the loads live
        return;
    }

    __shared__ uint32_t sBi[TI * WORDS];
    __shared__ int sNe[TI];           // row-nonempty flag (for diag fix)
    __shared__ float sPart[8][TI];
    int i0 = blockIdx.x * TI;

    if (tid < TI) sNe[tid] = 0;
    __syncthreads();
    for (int idx = tid; idx < TI * WORDS; idx += blockDim.x) {
        int r = idx >> 7, w = idx & (WORDS - 1);
        uint32_t v = g_bitsT[w * Nn + i0 + r];
        sBi[idx] = v;
        if (v) sNe[r] = 1;            // benign same-value race
    }
    __syncthreads();

    int jBeg = (blockIdx.y - 1) * (Nn / JSPLIT);
    int jEnd = jBeg + (Nn / JSPLIT);

    // this thread's share of sum(e) over its j set
    float sumE = 0.f;
    for (int j = jBeg + tid; j < jEnd; j += blockDim.x) sumE += g_e[j];

    uint32_t bi0[TI];
    float acc[TI];
    #pragma unroll
    for (int r = 0; r < TI; r++) { bi0[r] = sBi[r * WORDS]; acc[r] = sumE; }

    for (int j = jBeg + tid; j < jEnd; j += blockDim.x) {
        uint32_t b0 = g_bitsT[j];     // word-0 plane: 16KB, cache-resident
        unsigned zmask = 0;
        #pragma unroll
        for (int r = 0; r < TI; r++) {
            if (!(bi0[r] & b0)) zmask |= (1u << r);
        }
        if (zmask) {                  // rare (~1e-4 per pair)
            float e = g_e[j];
            do {
                int r = __ffs(zmask) - 1;
                zmask &= zmask - 1;
                bool hit = false;
                for (int w = 1; w < WORDS; w++)
                    if (sBi[r * WORDS + w] & g_bitsT[w * Nn + j]) { hit = true; break; }
                if (!hit) acc[r] -= e;
            } while (zmask);
        }
    }

    int lane = tid & 31, wid = tid >> 5;
    #pragma unroll
    for (int r = 0; r < TI; r++) {
        float v = acc[r];
        v += __shfl_down_sync(0xffffffffu, v, 16);
        v += __shfl_down_sync(0xffffffffu, v, 8);
        v += __shfl_down_sync(0xffffffffu, v, 4);
        v += __shfl_down_sync(0xffffffffu, v, 2);
        v += __shfl_down_sync(0xffffffffu, v, 1);
        if (lane == 0) sPart[wid][r] = v;
    }
    __syncthreads();
    if (tid < TI) {
        float s = 0.f;
        #pragma unroll
        for (int w = 0; w < 8; w++) s += sPart[w][tid];
        // diagonal correction, applied exactly once (by the owning chunk)
        int i = i0 + tid;
        if (i >= jBeg && i < jEnd && sNe[tid]) s -= g_e[i];
        atomicAdd(&g_agg[i], s);
    }
}

// ---------------------------------------------------------------------------
// K3: out[o] = b[o] + dot(W[o,:], agg)   (one warp per row; W is L2-hot)
// ---------------------------------------------------------------------------
__global__ void gemv_kernel(const float* __restrict__ Wm,
                            const float* __restrict__ bias,
                            float* __restrict__ out) {
    int gw = (blockIdx.x * blockDim.x + threadIdx.x) >> 5;
    int lane = threadIdx.x & 31;
    if (gw >= Nn) return;
    const float4* wr = (const float4*)(Wm + (size_t)gw * Nn);
    const float4* ar = (const float4*)g_agg;
    float s0 = 0.f, s1 = 0.f, s2 = 0.f, s3 = 0.f;
    #pragma unroll
    for (int k = 0; k < 32; k += 4) {
        float4 w0 = wr[lane + 32 * (k + 0)];
        float4 w1 = wr[lane + 32 * (k + 1)];
        float4 w2 = wr[lane + 32 * (k + 2)];
        float4 w3 = wr[lane + 32 * (k + 3)];
        float4 a0 = ar[lane + 32 * (k + 0)];
        float4 a1 = ar[lane + 32 * (k + 1)];
        float4 a2 = ar[lane + 32 * (k + 2)];
        float4 a3 = ar[lane + 32 * (k + 3)];
        s0 += w0.x * a0.x + w0.y * a0.y + w0.z * a0.z + w0.w * a0.w;
        s1 += w1.x * a1.x + w1.y * a1.y + w1.z * a1.z + w1.w * a1.w;
        s2 += w2.x * a2.x + w2.y * a2.y + w2.z * a2.z + w2.w * a2.w;
        s3 += w3.x * a3.x + w3.y * a3.y + w3.z * a3.z + w3.w * a3.w;
    }
    float s = (s0 + s1) + (s2 + s3);
    s += __shfl_down_sync(0xffffffffu, s, 16);
    s += __shfl_down_sync(0xffffffffu, s, 8);
    s += __shfl_down_sync(0xffffffffu, s, 4);
    s += __shfl_down_sync(0xffffffffu, s, 2);
    s += __shfl_down_sync(0xffffffffu, s, 1);
    if (lane == 0) out[gw] = s + bias[gw];
}

extern "C" void kernel_launch(void* const* d_in, const int* in_sizes, int n_in,
                              void* d_out, int out_size) {
    const float* A  = (const float*)d_in[0];  // adjacency [N,N]
    const float* E  = (const float*)d_in[1];  // edge_features [N,F]
    const float* Wm = (const float*)d_in[2];  // W [OUT,N]
    const float* b  = (const float*)d_in[3];  // b [OUT]
    float* out = (float*)d_out;

    prep_kernel<<<PACK_BLOCKS + ROWSUM_BLOCKS, 256>>>(A, E);
    dim3 g2(Nn / TI, JSPLIT + 1);             // y==0: W prefetch; y>=1: compute
    agg_kernel<<<g2, 256>>>(Wm);
    gemv_kernel<<<(Nn * 32) / 256, 256>>>(Wm, b, out);
}

// round 9
// speedup vs baseline: 1.2774x; 1.1238x over previous
#include <cuda_runtime.h>
#include <cstdint>

#define Nn 4096
#define WORDS 128          // 4096 bits / 32
#define TI 16              // i-rows per block (register blocking)
#define JSPLIT 4           // split j-range across blocks
#define PACK_BLOCKS 4096   // 16KB of A per block — balanced vs rowsum blocks
#define ROWSUM_BLOCKS Nn
#define PREF_BLOCKS 256    // L2-prefetch blocks for W inside agg launch

// Scratch (device globals — no allocation allowed)
__device__ uint32_t g_bitsT[WORDS * Nn];   // plane-major: word w of row j at [w*Nn + j]
__device__ __align__(16) uint32_t g_bitsR[Nn * WORDS];  // row-major copy (for i-tile loads)
__device__ __align__(16) float g_e[Nn];    // row sums of edge_features
__device__ __align__(16) float g_agg[Nn];  // aggregated[i]
__device__ float g_sink[PREF_BLOCKS];      // prefetch sink (never read)

// ---------------------------------------------------------------------------
// K1 (fused): blocks [0, PACK_BLOCKS) bit-pack adjacency (diag bit cleared).
//   Byte-per-thread: 2 LDG.128 per thread (8 cols -> 1 byte), reduce_or over
//   4-lane groups assembles each 32-bit word. Writes BOTH layouts:
//   plane-major (j-side streaming) and row-major (i-tile coalesced loads).
// blocks [PACK_BLOCKS, ...) row-sum E and zero g_agg.
// ---------------------------------------------------------------------------
__global__ void prep_kernel(const float* __restrict__ A,
                            const float* __restrict__ E) {
    if (blockIdx.x < PACK_BLOCKS) {
        int lane = threadIdx.x & 31;
        int warpid = blockIdx.x * 8 + (threadIdx.x >> 5);   // 0..32767
        const int NW = PACK_BLOCKS * 8;                     // 32768 warps
        unsigned q = lane >> 2;                             // word-in-group (0..7)
        unsigned grpmask = 0xFu << (q << 2);
        unsigned sh = (lane & 3) * 8;
        // groups of 256 cols: Nn*16 = 65536 total, exactly 2 per warp
        #pragma unroll
        for (int o = 0; o < 2; o++) {
            int gg  = warpid + o * NW;
            int j   = gg >> 4;
            int grp = gg & 15;
            int col = (grp << 8) + (lane << 3);
            const float4* p = (const float4*)(A + (size_t)j * Nn + col);
            float4 v0 = p[0];
            float4 v1 = p[1];
            unsigned byte = 0;
            if (v0.x == 1.0f && col + 0 != j) byte |= 1u;
            if (v0.y == 1.0f && col + 1 != j) byte |= 2u;
            if (v0.z == 1.0f && col + 2 != j) byte |= 4u;
            if (v0.w == 1.0f && col + 3 != j) byte |= 8u;
            if (v1.x == 1.0f && col + 4 != j) byte |= 16u;
            if (v1.y == 1.0f && col + 5 != j) byte |= 32u;
            if (v1.z == 1.0f && col + 6 != j) byte |= 64u;
            if (v1.w == 1.0f && col + 7 != j) byte |= 128u;
            unsigned word = __reduce_or_sync(grpmask, byte << sh);
            if ((lane & 3) == 0) {
                int w = (grp << 3) + (int)q;
                g_bitsT[w * Nn + j] = word;          // plane-major (j-side)
                g_bitsR[j * WORDS + w] = word;       // row-major (i-side, coalesced)
            }
        }
    } else {
        int j = blockIdx.x - PACK_BLOCKS;
        const float4* row = (const float4*)(E + (size_t)j * Nn);
        int tid = threadIdx.x;
        float s = 0.f;
        #pragma unroll
        for (int k = 0; k < 4; k++) {
            float4 v = row[tid + 256 * k];
            s += (v.x + v.y) + (v.z + v.w);
        }
        s += __shfl_down_sync(0xffffffffu, s, 16);
        s += __shfl_down_sync(0xffffffffu, s, 8);
        s += __shfl_down_sync(0xffffffffu, s, 4);
        s += __shfl_down_sync(0xffffffffu, s, 2);
        s += __shfl_down_sync(0xffffffffu, s, 1);
        __shared__ float sp[8];
        int lane = tid & 31, wid = tid >> 5;
        if (lane == 0) sp[wid] = s;
        __syncthreads();
        if (tid == 0) {
            float t = 0.f;
            #pragma unroll
            for (int k = 0; k < 8; k++) t += sp[k];
            g_e[j] = t;
            g_agg[j] = 0.f;
        }
    }
}

// ---------------------------------------------------------------------------
// K2: agg[i] = sum_j [ (i!=j) && (B_i & B_j != empty) ] * e[j]
// SUBTRACT-ON-MISS fast path (miss prob ~1e-4 per pair). i-tile loaded
// COALESCED from the row-major copy. Diagonal corrected once post-loop.
// blockIdx.y == 0: prefetch W into L2 (DRAM is otherwise idle here).
// ---------------------------------------------------------------------------
__global__ void agg_kernel(const float* __restrict__ Wm) {
    int tid = threadIdx.x;

    if (blockIdx.y == 0) {
        if (blockIdx.x >= PREF_BLOCKS) return;
        const float4* w4 = (const float4*)Wm;
        size_t base = (size_t)blockIdx.x * (Nn * Nn / 4 / PREF_BLOCKS) + tid;
        float s0 = 0.f, s1 = 0.f, s2 = 0.f, s3 = 0.f;
        #pragma unroll
        for (int k = 0; k < 64; k += 4) {
            float4 a = w4[base + (size_t)(k + 0) * 256];
            float4 b = w4[base + (size_t)(k + 1) * 256];
            float4 c = w4[base + (size_t)(k + 2) * 256];
            float4 d = w4[base + (size_t)(k + 3) * 256];
            s0 += a.x + a.y + a.z + a.w;
            s1 += b.x + b.y + b.z + b.w;
            s2 += c.x + c.y + c.z + c.w;
            s3 += d.x + d.y + d.z + d.w;
        }
        float s = (s0 + s1) + (s2 + s3);
        if (tid == 0) g_sink[blockIdx.x] = s;   // keep the loads live
        return;
    }

    __shared__ uint32_t sBi[TI * WORDS];
    __shared__ int sNe[TI];           // row-nonempty flag (for diag fix)
    __shared__ float sPart[8][TI];
    int i0 = blockIdx.x * TI;

    if (tid < TI) sNe[tid] = 0;
    __syncthreads();
    // coalesced i-tile load: TI*WORDS words = 8KB contiguous (uint4-wide)
    {
        const uint4* src = (const uint4*)(g_bitsR + (size_t)i0 * WORDS);
        uint4* dst = (uint4*)sBi;
        #pragma unroll
        for (int k = 0; k < (TI * WORDS / 4) / 256; k++) {
            uint4 v = src[tid + 256 * k];
            dst[tid + 256 * k] = v;
            if (v.x | v.y | v.z | v.w) sNe[(tid + 256 * k) >> 5] = 1;
        }
    }
    __syncthreads();

    int jBeg = (blockIdx.y - 1) * (Nn / JSPLIT);
    int jEnd = jBeg + (Nn / JSPLIT);

    // this thread's share of sum(e) over its j set
    float sumE = 0.f;
    for (int j = jBeg + tid; j < jEnd; j += blockDim.x) sumE += g_e[j];

    uint32_t bi0[TI];
    float acc[TI];
    #pragma unroll
    for (int r = 0; r < TI; r++) { bi0[r] = sBi[r * WORDS]; acc[r] = sumE; }

    for (int j = jBeg + tid; j < jEnd; j += blockDim.x) {
        uint32_t b0 = g_bitsT[j];     // word-0 plane: 16KB, cache-resident
        unsigned zmask = 0;
        #pragma unroll
        for (int r = 0; r < TI; r++) {
            if (!(bi0[r] & b0)) zmask |= (1u << r);
        }
        if (zmask) {                  // rare (~1e-4 per pair)
            float e = g_e[j];
            do {
                int r = __ffs(zmask) - 1;
                zmask &= zmask - 1;
                bool hit = false;
                for (int w = 1; w < WORDS; w++)
                    if (sBi[r * WORDS + w] & g_bitsT[w * Nn + j]) { hit = true; break; }
                if (!hit) acc[r] -= e;
            } while (zmask);
        }
    }

    int lane = tid & 31, wid = tid >> 5;
    #pragma unroll
    for (int r = 0; r < TI; r++) {
        float v = acc[r];
        v += __shfl_down_sync(0xffffffffu, v, 16);
        v += __shfl_down_sync(0xffffffffu, v, 8);
        v += __shfl_down_sync(0xffffffffu, v, 4);
        v += __shfl_down_sync(0xffffffffu, v, 2);
        v += __shfl_down_sync(0xffffffffu, v, 1);
        if (lane == 0) sPart[wid][r] = v;
    }
    __syncthreads();
    if (tid < TI) {
        float s = 0.f;
        #pragma unroll
        for (int w = 0; w < 8; w++) s += sPart[w][tid];
        // diagonal correction, applied exactly once (by the owning chunk)
        int i = i0 + tid;
        if (i >= jBeg && i < jEnd && sNe[tid]) s -= g_e[i];
        atomicAdd(&g_agg[i], s);
    }
}

// ---------------------------------------------------------------------------
// K3: out[o] = b[o] + dot(W[o,:], agg)   (one warp per row; W is L2-hot)
// ---------------------------------------------------------------------------
__global__ void gemv_kernel(const float* __restrict__ Wm,
                            const float* __restrict__ bias,
                            float* __restrict__ out) {
    int gw = (blockIdx.x * blockDim.x + threadIdx.x) >> 5;
    int lane = threadIdx.x & 31;
    if (gw >= Nn) return;
    const float4* wr = (const float4*)(Wm + (size_t)gw * Nn);
    const float4* ar = (const float4*)g_agg;
    float s0 = 0.f, s1 = 0.f, s2 = 0.f, s3 = 0.f;
    #pragma unroll
    for (int k = 0; k < 32; k += 4) {
        float4 w0 = wr[lane + 32 * (k + 0)];
        float4 w1 = wr[lane + 32 * (k + 1)];
        float4 w2 = wr[lane + 32 * (k + 2)];
        float4 w3 = wr[lane + 32 * (k + 3)];
        float4 a0 = ar[lane + 32 * (k + 0)];
        float4 a1 = ar[lane + 32 * (k + 1)];
        float4 a2 = ar[lane + 32 * (k + 2)];
        float4 a3 = ar[lane + 32 * (k + 3)];
        s0 += w0.x * a0.x + w0.y * a0.y + w0.z * a0.z + w0.w * a0.w;
        s1 += w1.x * a1.x + w1.y * a1.y + w1.z * a1.z + w1.w * a1.w;
        s2 += w2.x * a2.x + w2.y * a2.y + w2.z * a2.z + w2.w * a2.w;
        s3 += w3.x * a3.x + w3.y * a3.y + w3.z * a3.z + w3.w * a3.w;
    }
    float s = (s0 + s1) + (s2 + s3);
    s += __shfl_down_sync(0xffffffffu, s, 16);
    s += __shfl_down_sync(0xffffffffu, s, 8);
    s += __shfl_down_sync(0xffffffffu, s, 4);
    s += __shfl_down_sync(0xffffffffu, s, 2);
    s += __shfl_down_sync(0xffffffffu, s, 1);
    if (lane == 0) out[gw] = s + bias[gw];
}

extern "C" void kernel_launch(void* const* d_in, const int* in_sizes, int n_in,
                              void* d_out, int out_size) {
    const float* A  = (const float*)d_in[0];  // adjacency [N,N]
    const float* E  = (const float*)d_in[1];  // edge_features [N,F]
    const float* Wm = (const float*)d_in[2];  // W [OUT,N]
    const float* b  = (const float*)d_in[3];  // b [OUT]
    float* out = (float*)d_out;

    prep_kernel<<<PACK_BLOCKS + ROWSUM_BLOCKS, 256>>>(A, E);
    dim3 g2(Nn / TI, JSPLIT + 1);             // y==0: W prefetch; y>=1: compute
    agg_kernel<<<g2, 256>>>(Wm);
    gemv_kernel<<<(Nn * 32) / 256, 256>>>(Wm, b, out);
}

// round 10
// speedup vs baseline: 1.2870x; 1.0075x over previous
#include <cuda_runtime.h>
#include <cstdint>

#define Nn 4096
#define WORDS 128          // 4096 bits / 32
#define TI 16              // i-rows per block (register blocking)
#define JSPLIT 4           // split j-range across blocks
#define PACK_BLOCKS 4096   // 16KB of A per block — balanced vs rowsum blocks
#define ROWSUM_BLOCKS Nn

// Scratch (device globals — no allocation allowed)
__device__ uint32_t g_bitsT[WORDS * Nn];   // plane-major: word w of row j at [w*Nn + j]
__device__ __align__(16) uint32_t g_bitsR[Nn * WORDS];  // row-major copy (i-tile loads)
__device__ __align__(16) float g_e[Nn];    // row sums of edge_features
__device__ __align__(16) float g_agg[Nn];  // aggregated[i]

// ---------------------------------------------------------------------------
// K1 (fused): blocks [0, PACK_BLOCKS) bit-pack adjacency (diag bit cleared).
//   Byte-per-thread: 2 LDG.128 per thread (8 cols -> 1 byte), reduce_or over
//   4-lane groups. Writes plane-major (j-side) and row-major (i-side) copies.
// blocks [PACK_BLOCKS, ...) row-sum E and zero g_agg.
// ---------------------------------------------------------------------------
__global__ void prep_kernel(const float* __restrict__ A,
                            const float* __restrict__ E) {
    if (blockIdx.x < PACK_BLOCKS) {
        int lane = threadIdx.x & 31;
        int warpid = blockIdx.x * 8 + (threadIdx.x >> 5);   // 0..32767
        const int NW = PACK_BLOCKS * 8;                     // 32768 warps
        unsigned q = lane >> 2;                             // word-in-group (0..7)
        unsigned grpmask = 0xFu << (q << 2);
        unsigned sh = (lane & 3) * 8;
        // groups of 256 cols: Nn*16 = 65536 total, exactly 2 per warp
        #pragma unroll
        for (int o = 0; o < 2; o++) {
            int gg  = warpid + o * NW;
            int j   = gg >> 4;
            int grp = gg & 15;
            int col = (grp << 8) + (lane << 3);
            const float4* p = (const float4*)(A + (size_t)j * Nn + col);
            float4 v0 = p[0];
            float4 v1 = p[1];
            unsigned byte = 0;
            if (v0.x == 1.0f && col + 0 != j) byte |= 1u;
            if (v0.y == 1.0f && col + 1 != j) byte |= 2u;
            if (v0.z == 1.0f && col + 2 != j) byte |= 4u;
            if (v0.w == 1.0f && col + 3 != j) byte |= 8u;
            if (v1.x == 1.0f && col + 4 != j) byte |= 16u;
            if (v1.y == 1.0f && col + 5 != j) byte |= 32u;
            if (v1.z == 1.0f && col + 6 != j) byte |= 64u;
            if (v1.w == 1.0f && col + 7 != j) byte |= 128u;
            unsigned word = __reduce_or_sync(grpmask, byte << sh);
            if ((lane & 3) == 0) {
                int w = (grp << 3) + (int)q;
                g_bitsT[w * Nn + j] = word;          // plane-major (j-side)
                g_bitsR[j * WORDS + w] = word;       // row-major (i-side)
            }
        }
    } else {
        int j = blockIdx.x - PACK_BLOCKS;
        const float4* row = (const float4*)(E + (size_t)j * Nn);
        int tid = threadIdx.x;
        float s = 0.f;
        #pragma unroll
        for (int k = 0; k < 4; k++) {
            float4 v = row[tid + 256 * k];
            s += (v.x + v.y) + (v.z + v.w);
        }
        s += __shfl_down_sync(0xffffffffu, s, 16);
        s += __shfl_down_sync(0xffffffffu, s, 8);
        s += __shfl_down_sync(0xffffffffu, s, 4);
        s += __shfl_down_sync(0xffffffffu, s, 2);
        s += __shfl_down_sync(0xffffffffu, s, 1);
        __shared__ float sp[8];
        int lane = tid & 31, wid = tid >> 5;
        if (lane == 0) sp[wid] = s;
        __syncthreads();
        if (tid == 0) {
            float t = 0.f;
            #pragma unroll
            for (int k = 0; k < 8; k++) t += sp[k];
            g_e[j] = t;
            g_agg[j] = 0.f;
        }
    }
}

// ---------------------------------------------------------------------------
// K2: agg[i] = sum_j [ (i!=j) && (B_i & B_j != empty) ] * e[j]
// SUBTRACT-ON-MISS fast path (miss prob ~1e-4 per pair). i-tile loaded
// COALESCED from the row-major copy. Diagonal corrected once post-loop.
// Pure compute now — no prefetch sideband.
// ---------------------------------------------------------------------------
__global__ void agg_kernel() {
    int tid = threadIdx.x;
    __shared__ uint32_t sBi[TI * WORDS];
    __shared__ int sNe[TI];           // row-nonempty flag (for diag fix)
    __shared__ float sPart[8][TI];
    int i0 = blockIdx.x * TI;

    if (tid < TI) sNe[tid] = 0;
    __syncthreads();
    // coalesced i-tile load: TI*WORDS words = 8KB contiguous (uint4-wide)
    {
        const uint4* src = (const uint4*)(g_bitsR + (size_t)i0 * WORDS);
        uint4* dst = (uint4*)sBi;
        #pragma unroll
        for (int k = 0; k < (TI * WORDS / 4) / 256; k++) {
            uint4 v = src[tid + 256 * k];
            dst[tid + 256 * k] = v;
            if (v.x | v.y | v.z | v.w) sNe[(tid + 256 * k) >> 5] = 1;
        }
    }
    __syncthreads();

    int jBeg = blockIdx.y * (Nn / JSPLIT);
    int jEnd = jBeg + (Nn / JSPLIT);

    // this thread's share of sum(e) over its j set
    float sumE = 0.f;
    for (int j = jBeg + tid; j < jEnd; j += blockDim.x) sumE += g_e[j];

    uint32_t bi0[TI];
    float acc[TI];
    #pragma unroll
    for (int r = 0; r < TI; r++) { bi0[r] = sBi[r * WORDS]; acc[r] = sumE; }

    for (int j = jBeg + tid; j < jEnd; j += blockDim.x) {
        uint32_t b0 = g_bitsT[j];     // word-0 plane: 16KB, cache-resident
        unsigned zmask = 0;
        #pragma unroll
        for (int r = 0; r < TI; r++) {
            if (!(bi0[r] & b0)) zmask |= (1u << r);
        }
        if (zmask) {                  // rare (~1e-4 per pair)
            float e = g_e[j];
            do {
                int r = __ffs(zmask) - 1;
                zmask &= zmask - 1;
                bool hit = false;
                for (int w = 1; w < WORDS; w++)
                    if (sBi[r * WORDS + w] & g_bitsT[w * Nn + j]) { hit = true; break; }
                if (!hit) acc[r] -= e;
            } while (zmask);
        }
    }

    int lane = tid & 31, wid = tid >> 5;
    #pragma unroll
    for (int r = 0; r < TI; r++) {
        float v = acc[r];
        v += __shfl_down_sync(0xffffffffu, v, 16);
        v += __shfl_down_sync(0xffffffffu, v, 8);
        v += __shfl_down_sync(0xffffffffu, v, 4);
        v += __shfl_down_sync(0xffffffffu, v, 2);
        v += __shfl_down_sync(0xffffffffu, v, 1);
        if (lane == 0) sPart[wid][r] = v;
    }
    __syncthreads();
    if (tid < TI) {
        float s = 0.f;
        #pragma unroll
        for (int w = 0; w < 8; w++) s += sPart[w][tid];
        // diagonal correction, applied exactly once (by the owning chunk)
        int i = i0 + tid;
        if (i >= jBeg && i < jEnd && sNe[tid]) s -= g_e[i];
        atomicAdd(&g_agg[i], s);
    }
}

// ---------------------------------------------------------------------------
// K3: out[o] = b[o] + dot(W[o,:], agg)
// One BLOCK (256 threads) per output row -> 4096 blocks, full occupancy.
// Each thread: 4 independent float4 pairs (MLP=4), then block reduction.
// agg (16KB) is L2/L1-hot; W streams from DRAM at high utilization.
// ---------------------------------------------------------------------------
__global__ void gemv_kernel(const float* __restrict__ Wm,
                            const float* __restrict__ bias,
                            float* __restrict__ out) {
    int o = blockIdx.x;
    int tid = threadIdx.x;
    const float4* wr = (const float4*)(Wm + (size_t)o * Nn);
    const float4* ar = (const float4*)g_agg;

    float4 w0 = wr[tid];
    float4 w1 = wr[tid + 256];
    float4 w2 = wr[tid + 512];
    float4 w3 = wr[tid + 768];
    float4 a0 = ar[tid];
    float4 a1 = ar[tid + 256];
    float4 a2 = ar[tid + 512];
    float4 a3 = ar[tid + 768];
    float s0 = w0.x * a0.x + w0.y * a0.y + w0.z * a0.z + w0.w * a0.w;
    float s1 = w1.x * a1.x + w1.y * a1.y + w1.z * a1.z + w1.w * a1.w;
    float s2 = w2.x * a2.x + w2.y * a2.y + w2.z * a2.z + w2.w * a2.w;
    float s3 = w3.x * a3.x + w3.y * a3.y + w3.z * a3.z + w3.w * a3.w;
    float s = (s0 + s1) + (s2 + s3);

    s += __shfl_down_sync(0xffffffffu, s, 16);
    s += __shfl_down_sync(0xffffffffu, s, 8);
    s += __shfl_down_sync(0xffffffffu, s, 4);
    s += __shfl_down_sync(0xffffffffu, s, 2);
    s += __shfl_down_sync(0xffffffffu, s, 1);
    __shared__ float sp[8];
    int lane = tid & 31, wid = tid >> 5;
    if (lane == 0) sp[wid] = s;
    __syncthreads();
    if (tid == 0) {
        float t = 0.f;
        #pragma unroll
        for (int k = 0; k < 8; k++) t += sp[k];
        out[o] = t + bias[o];
    }
}

extern "C" void kernel_launch(void* const* d_in, const int* in_sizes, int n_in,
                              void* d_out, int out_size) {
    const float* A  = (const float*)d_in[0];  // adjacency [N,N]
    const float* E  = (const float*)d_in[1];  // edge_features [N,F]
    const float* Wm = (const float*)d_in[2];  // W [OUT,N]
    const float* b  = (const float*)d_in[3];  // b [OUT]
    float* out = (float*)d_out;

    prep_kernel<<<PACK_BLOCKS + ROWSUM_BLOCKS, 256>>>(A, E);
    dim3 g2(Nn / TI, JSPLIT);
    agg_kernel<<<g2, 256>>>();
    gemv_kernel<<<Nn, 256>>>(Wm, b, out);
}